// round 3
// baseline (speedup 1.0000x reference)
#include <cuda_runtime.h>
#include <cuda_bf16.h>
#include <cstdint>

#define N_NODES_MAX 50000
#define N_EDGES_MAX 500000
#define FDIM 128
#define F4 (FDIM / 4)

// Scratch (device globals — no allocation allowed)
__device__ float g_h[N_NODES_MAX * FDIM];    // h = x @ W
__device__ float g_dis[N_NODES_MAX];         // deg^{-1/2}
__device__ int   g_cnt[N_NODES_MAX];         // in-degree (edges only)
__device__ int   g_woff[N_NODES_MAX];        // segment cursor (start -> end after fill)
__device__ int   g_ebuf[N_EDGES_MAX];        // source row per edge, grouped by target
__device__ int   g_total;                    // global segment cursor
__device__ int   g_is32;

// ---------------------------------------------------------------------------
// setup: zero counters + cursor; thread 0 detects edge dtype.
// int64 indices are all < N_NODES; int32 data read as u64 -> >= 2^32 w.h.p.
__global__ void k_setup(const unsigned long long* __restrict__ e, int n) {
    int i = blockIdx.x * blockDim.x + threadIdx.x;
    if (i < n) g_cnt[i] = 0;
    if (i == 0) {
        g_total = 0;
        int f = 0;
        for (int j = 0; j < 256; j++)
            if (e[j] >= (unsigned long long)N_NODES_MAX) { f = 1; break; }
        g_is32 = f;
    }
}

__device__ __forceinline__ int load_idx(const void* __restrict__ e, long long pos) {
    if (g_is32) return ((const int*)e)[pos];
    return (int)(((const long long*)e)[pos]);
}

// count in-degree over edges (target = col = edge_index[1])
__global__ void k_count(const void* __restrict__ e, int ne) {
    int i = blockIdx.x * blockDim.x + threadIdx.x;
    if (i < ne) atomicAdd(&g_cnt[load_idx(e, (long long)ne + i)], 1);
}

// Reserve contiguous segments: warp-scan counts, one atomicAdd per warp.
// Also dis = rsqrt(deg+1). Segment ORDER across warps is arbitrary — fine,
// we only need per-target contiguity.
__global__ void __launch_bounds__(256) k_alloc(int n) {
    int i    = blockIdx.x * blockDim.x + threadIdx.x;
    int lane = threadIdx.x & 31;
    int c    = (i < n) ? g_cnt[i] : 0;
    if (i < n) g_dis[i] = rsqrtf((float)(c + 1));

    // inclusive warp scan
    int scan = c;
    #pragma unroll
    for (int off = 1; off < 32; off <<= 1) {
        int v = __shfl_up_sync(0xffffffffu, scan, off);
        if (lane >= off) scan += v;
    }
    int tot = __shfl_sync(0xffffffffu, scan, 31);
    int base = 0;
    if (lane == 31) base = atomicAdd(&g_total, tot);
    base = __shfl_sync(0xffffffffu, base, 31);
    if (i < n) g_woff[i] = base + (scan - c);   // exclusive within warp
}

// bucket fill: place source row of each edge into its target's segment
__global__ void k_bucket(const void* __restrict__ e, int ne) {
    int i = blockIdx.x * blockDim.x + threadIdx.x;
    if (i < ne) {
        int row = load_idx(e, i);
        int col = load_idx(e, (long long)ne + i);
        int pos = atomicAdd(&g_woff[col], 1);
        g_ebuf[pos] = row;
    }
}

// ---------------------------------------------------------------------------
// GEMM: g_h = x @ W.  128 threads = 128 output columns; 16 rows per block.
// Inner loop uses LDS.128 on the x tile (4 k-values per load) so FFMA issue
// dominates instead of scalar LDS.
#define ROWS_PB 16
__global__ void __launch_bounds__(FDIM) k_gemm(const float* __restrict__ x,
                                               const float* __restrict__ W,
                                               int n) {
    __shared__ __align__(16) float xs[ROWS_PB][FDIM];
    const int t  = threadIdx.x;
    const int r0 = blockIdx.x * ROWS_PB;

    #pragma unroll
    for (int r = 0; r < ROWS_PB; r++) {
        int row = r0 + r;
        xs[r][t] = (row < n) ? x[(size_t)row * FDIM + t] : 0.0f;
    }
    __syncthreads();

    float acc[ROWS_PB];
    #pragma unroll
    for (int r = 0; r < ROWS_PB; r++) acc[r] = 0.0f;

    #pragma unroll 2
    for (int k = 0; k < FDIM; k += 4) {
        float w0 = __ldg(&W[(size_t)(k + 0) * FDIM + t]);
        float w1 = __ldg(&W[(size_t)(k + 1) * FDIM + t]);
        float w2 = __ldg(&W[(size_t)(k + 2) * FDIM + t]);
        float w3 = __ldg(&W[(size_t)(k + 3) * FDIM + t]);
        #pragma unroll
        for (int r = 0; r < ROWS_PB; r++) {
            float4 xv = *(const float4*)&xs[r][k];
            acc[r] += xv.x * w0 + xv.y * w1 + xv.z * w2 + xv.w * w3;
        }
    }

    #pragma unroll
    for (int r = 0; r < ROWS_PB; r++) {
        int row = r0 + r;
        if (row < n) g_h[(size_t)row * FDIM + t] = acc[r];
    }
}

// ---------------------------------------------------------------------------
// Aggregate: one warp per target node. lane l owns float4 chunk l.
// out[i] = b + dis[i]^2 * h[i] + sum_j dis[i]*dis[row_j] * h[row_j]
__global__ void __launch_bounds__(256) k_aggregate(const float* __restrict__ b,
                                                   float* __restrict__ out,
                                                   int n) {
    int node = (int)((blockIdx.x * (long long)blockDim.x + threadIdx.x) >> 5);
    int lane = threadIdx.x & 31;
    if (node >= n) return;

    float s   = g_dis[node];
    int   end = g_woff[node];            // after bucket fill: start + cnt
    int   cnt = g_cnt[node];
    int   j   = end - cnt;

    const float4* __restrict__ h4 = (const float4*)g_h;

    float4 acc = ((const float4*)b)[lane];
    {
        float ss = s * s;
        float4 hv = h4[(size_t)node * 32 + lane];
        acc.x += ss * hv.x; acc.y += ss * hv.y;
        acc.z += ss * hv.z; acc.w += ss * hv.w;
    }

    for (; j + 1 < end; j += 2) {
        int r0 = g_ebuf[j];
        int r1 = g_ebuf[j + 1];
        float n0 = s * g_dis[r0];
        float n1 = s * g_dis[r1];
        float4 v0 = h4[(size_t)r0 * 32 + lane];
        float4 v1 = h4[(size_t)r1 * 32 + lane];
        acc.x += n0 * v0.x + n1 * v1.x;
        acc.y += n0 * v0.y + n1 * v1.y;
        acc.z += n0 * v0.z + n1 * v1.z;
        acc.w += n0 * v0.w + n1 * v1.w;
    }
    if (j < end) {
        int r0 = g_ebuf[j];
        float n0 = s * g_dis[r0];
        float4 v0 = h4[(size_t)r0 * 32 + lane];
        acc.x += n0 * v0.x; acc.y += n0 * v0.y;
        acc.z += n0 * v0.z; acc.w += n0 * v0.w;
    }

    ((float4*)out)[(size_t)node * 32 + lane] = acc;
}

// ---------------------------------------------------------------------------
extern "C" void kernel_launch(void* const* d_in, const int* in_sizes, int n_in,
                              void* d_out, int out_size) {
    const float* x  = (const float*)d_in[0];
    const void*  ei = d_in[1];
    const float* W  = (const float*)d_in[2];
    const float* b  = (const float*)d_in[3];
    float* out = (float*)d_out;

    const int n  = in_sizes[0] / FDIM;   // 50000
    const int ne = in_sizes[1] / 2;      // 500000

    k_setup <<<(n + 255) / 256, 256>>>((const unsigned long long*)ei, n);
    k_count <<<(ne + 255) / 256, 256>>>(ei, ne);
    k_alloc <<<(n + 255) / 256, 256>>>(n);
    k_bucket<<<(ne + 255) / 256, 256>>>(ei, ne);
    k_gemm  <<<(n + ROWS_PB - 1) / ROWS_PB, FDIM>>>(x, W, n);
    k_aggregate<<<(n * 32 + 255) / 256, 256>>>(b, out, n);   // launch idx 5 -> profiled
}

// round 4
// speedup vs baseline: 1.1186x; 1.1186x over previous
#include <cuda_runtime.h>
#include <cuda_bf16.h>
#include <cstdint>

#define N_NODES_MAX 50000
#define N_EDGES_MAX 500000
#define FDIM 128

// Scratch (device globals — no allocation allowed)
__device__ float g_h[N_NODES_MAX * FDIM];    // h = x @ W
__device__ float g_dis[N_NODES_MAX];         // deg^{-1/2}
__device__ int   g_cnt[N_NODES_MAX];         // in-degree (edges only)
__device__ int   g_woff[N_NODES_MAX];        // segment cursor (start -> end after fill)
__device__ int   g_ebuf[N_EDGES_MAX];        // source row per edge, grouped by target
__device__ int   g_total;                    // global segment cursor
__device__ int   g_is32;

// ---------------------------------------------------------------------------
// setup: zero counters + cursor; block 0 detects edge dtype IN PARALLEL.
// int64 indices are all < N_NODES; int32 data read as u64 -> >= 2^32 w.h.p.
__global__ void k_setup(const unsigned long long* __restrict__ e, int n) {
    int i = blockIdx.x * blockDim.x + threadIdx.x;
    if (i < n) g_cnt[i] = 0;
    if (blockIdx.x == 0) {
        int bad = (e[threadIdx.x] >= (unsigned long long)N_NODES_MAX) ? 1 : 0;
        int any = __syncthreads_or(bad);
        if (threadIdx.x == 0) { g_is32 = any; g_total = 0; }
    }
}

__device__ __forceinline__ int load_idx(const void* __restrict__ e, long long pos) {
    if (g_is32) return ((const int*)e)[pos];
    return (int)(((const long long*)e)[pos]);
}

// count in-degree over edges (target = col = edge_index[1])
__global__ void k_count(const void* __restrict__ e, int ne) {
    int i = blockIdx.x * blockDim.x + threadIdx.x;
    if (i < ne) atomicAdd(&g_cnt[load_idx(e, (long long)ne + i)], 1);
}

// Reserve contiguous segments: warp-scan counts, one atomicAdd per warp.
// Also dis = rsqrt(deg+1). Cross-warp segment order is arbitrary (fine).
__global__ void __launch_bounds__(256) k_alloc(int n) {
    int i    = blockIdx.x * blockDim.x + threadIdx.x;
    int lane = threadIdx.x & 31;
    int c    = (i < n) ? g_cnt[i] : 0;
    if (i < n) g_dis[i] = rsqrtf((float)(c + 1));

    int scan = c;
    #pragma unroll
    for (int off = 1; off < 32; off <<= 1) {
        int v = __shfl_up_sync(0xffffffffu, scan, off);
        if (lane >= off) scan += v;
    }
    int tot = __shfl_sync(0xffffffffu, scan, 31);
    int base = 0;
    if (lane == 31) base = atomicAdd(&g_total, tot);
    base = __shfl_sync(0xffffffffu, base, 31);
    if (i < n) g_woff[i] = base + (scan - c);
}

// bucket fill: place source row of each edge into its target's segment
__global__ void k_bucket(const void* __restrict__ e, int ne) {
    int i = blockIdx.x * blockDim.x + threadIdx.x;
    if (i < ne) {
        int row = load_idx(e, i);
        int col = load_idx(e, (long long)ne + i);
        int pos = atomicAdd(&g_woff[col], 1);
        g_ebuf[pos] = row;
    }
}

// ---------------------------------------------------------------------------
// GEMM: g_h = x @ W.  128 threads = 128 output columns; 16 rows per block.
#define ROWS_PB 16
__global__ void __launch_bounds__(FDIM) k_gemm(const float* __restrict__ x,
                                               const float* __restrict__ W,
                                               int n) {
    __shared__ __align__(16) float xs[ROWS_PB][FDIM];
    const int t  = threadIdx.x;
    const int r0 = blockIdx.x * ROWS_PB;

    #pragma unroll
    for (int r = 0; r < ROWS_PB; r++) {
        int row = r0 + r;
        xs[r][t] = (row < n) ? x[(size_t)row * FDIM + t] : 0.0f;
    }
    __syncthreads();

    float acc[ROWS_PB];
    #pragma unroll
    for (int r = 0; r < ROWS_PB; r++) acc[r] = 0.0f;

    #pragma unroll 2
    for (int k = 0; k < FDIM; k += 4) {
        float w0 = __ldg(&W[(size_t)(k + 0) * FDIM + t]);
        float w1 = __ldg(&W[(size_t)(k + 1) * FDIM + t]);
        float w2 = __ldg(&W[(size_t)(k + 2) * FDIM + t]);
        float w3 = __ldg(&W[(size_t)(k + 3) * FDIM + t]);
        #pragma unroll
        for (int r = 0; r < ROWS_PB; r++) {
            float4 xv = *(const float4*)&xs[r][k];
            acc[r] += xv.x * w0 + xv.y * w1 + xv.z * w2 + xv.w * w3;
        }
    }

    #pragma unroll
    for (int r = 0; r < ROWS_PB; r++) {
        int row = r0 + r;
        if (row < n) g_h[(size_t)row * FDIM + t] = acc[r];
    }
}

// ---------------------------------------------------------------------------
// Aggregate: one warp per target node. lane l owns float4 chunk l.
// out[i] = b + dis[i]^2 * h[i] + sum_j dis[i]*dis[row_j] * h[row_j]
__global__ void __launch_bounds__(256) k_aggregate(const float* __restrict__ b,
                                                   float* __restrict__ out,
                                                   int n) {
    int node = (int)((blockIdx.x * (long long)blockDim.x + threadIdx.x) >> 5);
    int lane = threadIdx.x & 31;
    if (node >= n) return;

    float s   = g_dis[node];
    int   end = g_woff[node];
    int   cnt = g_cnt[node];
    int   j   = end - cnt;

    const float4* __restrict__ h4 = (const float4*)g_h;

    float4 acc = ((const float4*)b)[lane];
    {
        float ss = s * s;
        float4 hv = h4[(size_t)node * 32 + lane];
        acc.x += ss * hv.x; acc.y += ss * hv.y;
        acc.z += ss * hv.z; acc.w += ss * hv.w;
    }

    // 4-wide unroll for gather MLP
    for (; j + 3 < end; j += 4) {
        int r0 = g_ebuf[j], r1 = g_ebuf[j + 1], r2 = g_ebuf[j + 2], r3 = g_ebuf[j + 3];
        float n0 = s * g_dis[r0], n1 = s * g_dis[r1];
        float n2 = s * g_dis[r2], n3 = s * g_dis[r3];
        float4 v0 = h4[(size_t)r0 * 32 + lane];
        float4 v1 = h4[(size_t)r1 * 32 + lane];
        float4 v2 = h4[(size_t)r2 * 32 + lane];
        float4 v3 = h4[(size_t)r3 * 32 + lane];
        acc.x += n0 * v0.x + n1 * v1.x + n2 * v2.x + n3 * v3.x;
        acc.y += n0 * v0.y + n1 * v1.y + n2 * v2.y + n3 * v3.y;
        acc.z += n0 * v0.z + n1 * v1.z + n2 * v2.z + n3 * v3.z;
        acc.w += n0 * v0.w + n1 * v1.w + n2 * v2.w + n3 * v3.w;
    }
    for (; j < end; j++) {
        int r0 = g_ebuf[j];
        float n0 = s * g_dis[r0];
        float4 v0 = h4[(size_t)r0 * 32 + lane];
        acc.x += n0 * v0.x; acc.y += n0 * v0.y;
        acc.z += n0 * v0.z; acc.w += n0 * v0.w;
    }

    ((float4*)out)[(size_t)node * 32 + lane] = acc;
}

// ---------------------------------------------------------------------------
extern "C" void kernel_launch(void* const* d_in, const int* in_sizes, int n_in,
                              void* d_out, int out_size) {
    const float* x  = (const float*)d_in[0];
    const void*  ei = d_in[1];
    const float* W  = (const float*)d_in[2];
    const float* b  = (const float*)d_in[3];
    float* out = (float*)d_out;

    const int n  = in_sizes[0] / FDIM;   // 50000
    const int ne = in_sizes[1] / 2;      // 500000

    // Side stream + events for capture-legal fork/join (created once; no
    // device memory involved). GEMM is independent of the CSR-build chain.
    static cudaStream_t s_side = nullptr;
    static cudaEvent_t  ev_fork = nullptr, ev_join = nullptr;
    if (s_side == nullptr) {
        cudaStreamCreateWithFlags(&s_side, cudaStreamNonBlocking);
        cudaEventCreateWithFlags(&ev_fork, cudaEventDisableTiming);
        cudaEventCreateWithFlags(&ev_join, cudaEventDisableTiming);
    }

    // fork: gemm runs concurrently with the CSR build
    cudaEventRecord(ev_fork, 0);
    cudaStreamWaitEvent(s_side, ev_fork, 0);
    k_gemm<<<(n + ROWS_PB - 1) / ROWS_PB, FDIM, 0, s_side>>>(x, W, n);
    cudaEventRecord(ev_join, s_side);

    // main chain: CSR build
    k_setup <<<(n + 255) / 256, 256>>>((const unsigned long long*)ei, n);
    k_count <<<(ne + 255) / 256, 256>>>(ei, ne);
    k_alloc <<<(n + 255) / 256, 256>>>(n);
    k_bucket<<<(ne + 255) / 256, 256>>>(ei, ne);

    // join, then aggregate (needs both h and the CSR)
    cudaStreamWaitEvent(0, ev_join, 0);
    k_aggregate<<<(n * 32 + 255) / 256, 256>>>(b, out, n);
}

// round 5
// speedup vs baseline: 1.1724x; 1.0481x over previous
#include <cuda_runtime.h>
#include <cuda_bf16.h>
#include <cstdint>

#define N_NODES_MAX 50000
#define N_EDGES_MAX 500000
#define FDIM 128

// Scratch (device globals — no allocation allowed)
__device__ float g_h[N_NODES_MAX * FDIM];    // h = x @ W
__device__ float g_dis[N_NODES_MAX];         // deg^{-1/2}
__device__ int   g_cnt[N_NODES_MAX];         // in-degree (edges only)
__device__ int   g_woff[N_NODES_MAX];        // segment cursor (start -> end after fill)
__device__ int   g_ebuf[N_EDGES_MAX];        // source row per edge, grouped by target
__device__ int   g_total;                    // global segment cursor
__device__ int   g_is32;

// ---------------------------------------------------------------------------
// setup: zero counters + cursor; block 0 detects edge dtype in parallel.
// int64 indices are all < N_NODES; int32 data read as u64 -> >= 2^32 w.h.p.
__global__ void k_setup(const unsigned long long* __restrict__ e, int n) {
    int i = blockIdx.x * blockDim.x + threadIdx.x;
    if (i < n) g_cnt[i] = 0;
    if (blockIdx.x == 0) {
        int bad = (e[threadIdx.x] >= (unsigned long long)N_NODES_MAX) ? 1 : 0;
        int any = __syncthreads_or(bad);
        if (threadIdx.x == 0) { g_is32 = any; g_total = 0; }
    }
}

__device__ __forceinline__ int load_idx(const void* __restrict__ e, long long pos) {
    if (g_is32) return ((const int*)e)[pos];
    return (int)(((const long long*)e)[pos]);
}

// count in-degree over edges (target = col = edge_index[1])
__global__ void k_count(const void* __restrict__ e, int ne) {
    int i = blockIdx.x * blockDim.x + threadIdx.x;
    if (i < ne) atomicAdd(&g_cnt[load_idx(e, (long long)ne + i)], 1);
}

// Reserve contiguous segments: warp-scan counts, one atomicAdd per warp.
// Also dis = rsqrt(deg+1). Cross-warp segment order is arbitrary (fine).
__global__ void __launch_bounds__(256) k_alloc(int n) {
    int i    = blockIdx.x * blockDim.x + threadIdx.x;
    int lane = threadIdx.x & 31;
    int c    = (i < n) ? g_cnt[i] : 0;
    if (i < n) g_dis[i] = rsqrtf((float)(c + 1));

    int scan = c;
    #pragma unroll
    for (int off = 1; off < 32; off <<= 1) {
        int v = __shfl_up_sync(0xffffffffu, scan, off);
        if (lane >= off) scan += v;
    }
    int tot = __shfl_sync(0xffffffffu, scan, 31);
    int base = 0;
    if (lane == 31) base = atomicAdd(&g_total, tot);
    base = __shfl_sync(0xffffffffu, base, 31);
    if (i < n) g_woff[i] = base + (scan - c);
}

// bucket fill: place source row of each edge into its target's segment
__global__ void k_bucket(const void* __restrict__ e, int ne) {
    int i = blockIdx.x * blockDim.x + threadIdx.x;
    if (i < ne) {
        int row = load_idx(e, i);
        int col = load_idx(e, (long long)ne + i);
        int pos = atomicAdd(&g_woff[col], 1);
        g_ebuf[pos] = row;
    }
}

// ---------------------------------------------------------------------------
// GEMM: g_h = x @ W.  128 threads = 128 output columns; 16 rows per block.
// Inner loop uses Blackwell packed fma.rn.f32x2 (PTX-only; 2 fp32 FMA lanes
// per instruction) — each packed accumulator carries two k-partial sums,
// reduced horizontally at the end.
#define ROWS_PB 16

__device__ __forceinline__ void fma2(unsigned long long& d,
                                     unsigned long long a,
                                     unsigned long long b) {
    asm("fma.rn.f32x2 %0, %1, %2, %0;" : "+l"(d) : "l"(a), "l"(b));
}

__global__ void __launch_bounds__(FDIM) k_gemm(const float* __restrict__ x,
                                               const float* __restrict__ W,
                                               int n) {
    __shared__ __align__(16) float xs[ROWS_PB][FDIM];
    const int t  = threadIdx.x;
    const int r0 = blockIdx.x * ROWS_PB;

    #pragma unroll
    for (int r = 0; r < ROWS_PB; r++) {
        int row = r0 + r;
        xs[r][t] = (row < n) ? x[(size_t)row * FDIM + t] : 0.0f;
    }
    __syncthreads();

    unsigned long long acc2[ROWS_PB];
    #pragma unroll
    for (int r = 0; r < ROWS_PB; r++) acc2[r] = 0ull;

    #pragma unroll 2
    for (int k = 0; k < FDIM; k += 4) {
        float w0 = __ldg(&W[(size_t)(k + 0) * FDIM + t]);
        float w1 = __ldg(&W[(size_t)(k + 1) * FDIM + t]);
        float w2 = __ldg(&W[(size_t)(k + 2) * FDIM + t]);
        float w3 = __ldg(&W[(size_t)(k + 3) * FDIM + t]);
        unsigned long long w01, w23;
        asm("mov.b64 %0, {%1, %2};" : "=l"(w01) : "f"(w0), "f"(w1));
        asm("mov.b64 %0, {%1, %2};" : "=l"(w23) : "f"(w2), "f"(w3));
        #pragma unroll
        for (int r = 0; r < ROWS_PB; r++) {
            const unsigned long long* xp =
                (const unsigned long long*)&xs[r][k];   // 16B-aligned
            fma2(acc2[r], xp[0], w01);
            fma2(acc2[r], xp[1], w23);
        }
    }

    #pragma unroll
    for (int r = 0; r < ROWS_PB; r++) {
        int row = r0 + r;
        if (row < n) {
            float lo, hi;
            asm("mov.b64 {%0, %1}, %2;" : "=f"(lo), "=f"(hi) : "l"(acc2[r]));
            g_h[(size_t)row * FDIM + t] = lo + hi;
        }
    }
}

// ---------------------------------------------------------------------------
// Aggregate: one warp per target node. lane l owns float4 chunk l.
// out[i] = b + dis[i]^2 * h[i] + sum_j dis[i]*dis[row_j] * h[row_j]
__global__ void __launch_bounds__(256) k_aggregate(const float* __restrict__ b,
                                                   float* __restrict__ out,
                                                   int n) {
    int node = (int)((blockIdx.x * (long long)blockDim.x + threadIdx.x) >> 5);
    int lane = threadIdx.x & 31;
    if (node >= n) return;

    float s   = g_dis[node];
    int   end = g_woff[node];
    int   cnt = g_cnt[node];
    int   j   = end - cnt;

    const float4* __restrict__ h4 = (const float4*)g_h;

    float4 acc = ((const float4*)b)[lane];
    {
        float ss = s * s;
        float4 hv = h4[(size_t)node * 32 + lane];
        acc.x += ss * hv.x; acc.y += ss * hv.y;
        acc.z += ss * hv.z; acc.w += ss * hv.w;
    }

    for (; j + 3 < end; j += 4) {
        int r0 = g_ebuf[j], r1 = g_ebuf[j + 1], r2 = g_ebuf[j + 2], r3 = g_ebuf[j + 3];
        float n0 = s * g_dis[r0], n1 = s * g_dis[r1];
        float n2 = s * g_dis[r2], n3 = s * g_dis[r3];
        float4 v0 = h4[(size_t)r0 * 32 + lane];
        float4 v1 = h4[(size_t)r1 * 32 + lane];
        float4 v2 = h4[(size_t)r2 * 32 + lane];
        float4 v3 = h4[(size_t)r3 * 32 + lane];
        acc.x += n0 * v0.x + n1 * v1.x + n2 * v2.x + n3 * v3.x;
        acc.y += n0 * v0.y + n1 * v1.y + n2 * v2.y + n3 * v3.y;
        acc.z += n0 * v0.z + n1 * v1.z + n2 * v2.z + n3 * v3.z;
        acc.w += n0 * v0.w + n1 * v1.w + n2 * v2.w + n3 * v3.w;
    }
    for (; j < end; j++) {
        int r0 = g_ebuf[j];
        float n0 = s * g_dis[r0];
        float4 v0 = h4[(size_t)r0 * 32 + lane];
        acc.x += n0 * v0.x; acc.y += n0 * v0.y;
        acc.z += n0 * v0.z; acc.w += n0 * v0.w;
    }

    ((float4*)out)[(size_t)node * 32 + lane] = acc;
}

// ---------------------------------------------------------------------------
extern "C" void kernel_launch(void* const* d_in, const int* in_sizes, int n_in,
                              void* d_out, int out_size) {
    const float* x  = (const float*)d_in[0];
    const void*  ei = d_in[1];
    const float* W  = (const float*)d_in[2];
    const float* b  = (const float*)d_in[3];
    float* out = (float*)d_out;

    const int n  = in_sizes[0] / FDIM;   // 50000
    const int ne = in_sizes[1] / 2;      // 500000

    static cudaStream_t s_side = nullptr;
    static cudaEvent_t  ev_fork = nullptr, ev_join = nullptr;
    if (s_side == nullptr) {
        cudaStreamCreateWithFlags(&s_side, cudaStreamNonBlocking);
        cudaEventCreateWithFlags(&ev_fork, cudaEventDisableTiming);
        cudaEventCreateWithFlags(&ev_join, cudaEventDisableTiming);
    }

    // fork: gemm runs concurrently with the CSR build
    cudaEventRecord(ev_fork, 0);
    cudaStreamWaitEvent(s_side, ev_fork, 0);
    k_gemm<<<(n + ROWS_PB - 1) / ROWS_PB, FDIM, 0, s_side>>>(x, W, n);
    cudaEventRecord(ev_join, s_side);

    // main chain: CSR build
    k_setup <<<(n + 255) / 256, 256>>>((const unsigned long long*)ei, n);
    k_count <<<(ne + 255) / 256, 256>>>(ei, ne);
    k_alloc <<<(n + 255) / 256, 256>>>(n);
    k_bucket<<<(ne + 255) / 256, 256>>>(ei, ne);

    // join, then aggregate (needs both h and the CSR)
    cudaStreamWaitEvent(0, ev_join, 0);
    k_aggregate<<<(n * 32 + 255) / 256, 256>>>(b, out, n);
}

// round 6
// speedup vs baseline: 1.1891x; 1.0143x over previous
#include <cuda_runtime.h>
#include <cuda_bf16.h>
#include <cstdint>

#define N_NODES_MAX 50000
#define N_EDGES_MAX 500000
#define FDIM 128
#define CAP 128                    // fixed bucket capacity per node
#define SPILL_MAX N_EDGES_MAX      // worst-case spill storage

// Scratch (device globals — no allocation allowed)
__device__ float g_h[N_NODES_MAX * FDIM];      // h = x @ W
__device__ float g_dis[N_NODES_MAX];           // deg^{-1/2}
__device__ int   g_cnt[N_NODES_MAX];           // in-degree (edges only)
__device__ int   g_ebuf[N_NODES_MAX * CAP];    // bucketed source rows
__device__ int   g_spill[SPILL_MAX * 2];       // (row,col) overflow pairs
__device__ int   g_spill_n;
__device__ int   g_is32;

// ---------------------------------------------------------------------------
// setup: zero counters; block 0 detects edge dtype in parallel.
// int64 indices are all < N_NODES; int32 data read as u64 -> >= 2^32 w.h.p.
__global__ void k_setup(const unsigned long long* __restrict__ e, int n) {
    int i = blockIdx.x * blockDim.x + threadIdx.x;
    if (i < n) g_cnt[i] = 0;
    if (blockIdx.x == 0) {
        int bad = (e[threadIdx.x] >= (unsigned long long)N_NODES_MAX) ? 1 : 0;
        int any = __syncthreads_or(bad);
        if (threadIdx.x == 0) { g_is32 = any; g_spill_n = 0; }
    }
}

__device__ __forceinline__ int load_idx(const void* __restrict__ e, long long pos) {
    if (g_is32) return ((const int*)e)[pos];
    return (int)(((const long long*)e)[pos]);
}

// ---------------------------------------------------------------------------
// bucket fill, 4 edges per thread for atomic-latency MLP.
// slot self-allocation: atomicAdd on cnt returns the slot index.
#define EPT 4
__global__ void __launch_bounds__(256) k_bucket(const void* __restrict__ e, int ne) {
    int base = (blockIdx.x * blockDim.x + threadIdx.x) * EPT;
    int rows[EPT], cols[EPT], slots[EPT];
    int m = 0;
    #pragma unroll
    for (int u = 0; u < EPT; u++) {
        int i = base + u;
        if (i < ne) {
            rows[m] = load_idx(e, i);
            cols[m] = load_idx(e, (long long)ne + i);
            m++;
        }
    }
    #pragma unroll
    for (int u = 0; u < EPT; u++)
        if (u < m) slots[u] = atomicAdd(&g_cnt[cols[u]], 1);
    #pragma unroll
    for (int u = 0; u < EPT; u++) {
        if (u < m) {
            if (slots[u] < CAP) {
                g_ebuf[(size_t)cols[u] * CAP + slots[u]] = rows[u];
            } else {
                int p = atomicAdd(&g_spill_n, 1);
                g_spill[2 * p]     = rows[u];
                g_spill[2 * p + 1] = cols[u];
            }
        }
    }
}

// dis = rsqrt(deg_in + 1)
__global__ void k_dis(int n) {
    int i = blockIdx.x * blockDim.x + threadIdx.x;
    if (i < n) g_dis[i] = rsqrtf((float)(g_cnt[i] + 1));
}

// ---------------------------------------------------------------------------
// GEMM: g_h = x @ W.  128 threads = 128 output columns; 16 rows per block.
// LDS.128 yields two packed f32x2 operands per load; fma.rn.f32x2 does
// 2 fp32 FMA lanes/inst. Packed accumulators reduced horizontally at the end.
#define ROWS_PB 16

__device__ __forceinline__ void fma2(unsigned long long& d,
                                     unsigned long long a,
                                     unsigned long long b) {
    asm("fma.rn.f32x2 %0, %1, %2, %0;" : "+l"(d) : "l"(a), "l"(b));
}

__global__ void __launch_bounds__(FDIM) k_gemm(const float* __restrict__ x,
                                               const float* __restrict__ W,
                                               int n) {
    __shared__ __align__(16) float xs[ROWS_PB][FDIM];
    const int t  = threadIdx.x;
    const int r0 = blockIdx.x * ROWS_PB;

    #pragma unroll
    for (int r = 0; r < ROWS_PB; r++) {
        int row = r0 + r;
        xs[r][t] = (row < n) ? x[(size_t)row * FDIM + t] : 0.0f;
    }
    __syncthreads();

    unsigned long long acc2[ROWS_PB];
    #pragma unroll
    for (int r = 0; r < ROWS_PB; r++) acc2[r] = 0ull;

    #pragma unroll 2
    for (int k = 0; k < FDIM; k += 4) {
        float w0 = __ldg(&W[(size_t)(k + 0) * FDIM + t]);
        float w1 = __ldg(&W[(size_t)(k + 1) * FDIM + t]);
        float w2 = __ldg(&W[(size_t)(k + 2) * FDIM + t]);
        float w3 = __ldg(&W[(size_t)(k + 3) * FDIM + t]);
        unsigned long long w01, w23;
        asm("mov.b64 %0, {%1, %2};" : "=l"(w01) : "f"(w0), "f"(w1));
        asm("mov.b64 %0, {%1, %2};" : "=l"(w23) : "f"(w2), "f"(w3));
        #pragma unroll
        for (int r = 0; r < ROWS_PB; r++) {
            ulonglong2 xv = *(const ulonglong2*)&xs[r][k];   // LDS.128
            fma2(acc2[r], xv.x, w01);
            fma2(acc2[r], xv.y, w23);
        }
    }

    #pragma unroll
    for (int r = 0; r < ROWS_PB; r++) {
        int row = r0 + r;
        if (row < n) {
            float lo, hi;
            asm("mov.b64 {%0, %1}, %2;" : "=f"(lo), "=f"(hi) : "l"(acc2[r]));
            g_h[(size_t)row * FDIM + t] = lo + hi;
        }
    }
}

// ---------------------------------------------------------------------------
// Aggregate: one warp per target node. lane l owns float4 chunk l.
// out[i] = b + dis[i]^2 * h[i] + sum_j dis[i]*dis[row_j] * h[row_j]
// Nodes whose bucket overflowed (cnt > CAP) additionally scan the spill list
// (empty in practice).
__global__ void __launch_bounds__(256) k_aggregate(const float* __restrict__ b,
                                                   float* __restrict__ out,
                                                   int n) {
    int node = (int)((blockIdx.x * (long long)blockDim.x + threadIdx.x) >> 5);
    int lane = threadIdx.x & 31;
    if (node >= n) return;

    float s   = g_dis[node];
    int   cnt = g_cnt[node];
    int   m   = cnt < CAP ? cnt : CAP;
    const int* __restrict__ seg = g_ebuf + (size_t)node * CAP;

    const float4* __restrict__ h4 = (const float4*)g_h;

    float4 acc = ((const float4*)b)[lane];
    {
        float ss = s * s;
        float4 hv = h4[(size_t)node * 32 + lane];
        acc.x += ss * hv.x; acc.y += ss * hv.y;
        acc.z += ss * hv.z; acc.w += ss * hv.w;
    }

    int j = 0;
    for (; j + 3 < m; j += 4) {
        int r0 = seg[j], r1 = seg[j + 1], r2 = seg[j + 2], r3 = seg[j + 3];
        float n0 = s * g_dis[r0], n1 = s * g_dis[r1];
        float n2 = s * g_dis[r2], n3 = s * g_dis[r3];
        float4 v0 = h4[(size_t)r0 * 32 + lane];
        float4 v1 = h4[(size_t)r1 * 32 + lane];
        float4 v2 = h4[(size_t)r2 * 32 + lane];
        float4 v3 = h4[(size_t)r3 * 32 + lane];
        acc.x += n0 * v0.x + n1 * v1.x + n2 * v2.x + n3 * v3.x;
        acc.y += n0 * v0.y + n1 * v1.y + n2 * v2.y + n3 * v3.y;
        acc.z += n0 * v0.z + n1 * v1.z + n2 * v2.z + n3 * v3.z;
        acc.w += n0 * v0.w + n1 * v1.w + n2 * v2.w + n3 * v3.w;
    }
    for (; j < m; j++) {
        int r0 = seg[j];
        float n0 = s * g_dis[r0];
        float4 v0 = h4[(size_t)r0 * 32 + lane];
        acc.x += n0 * v0.x; acc.y += n0 * v0.y;
        acc.z += n0 * v0.z; acc.w += n0 * v0.w;
    }

    if (cnt > CAP) {                       // overflow path: scan spill list
        int sn = g_spill_n;
        for (int p = 0; p < sn; p++) {
            if (g_spill[2 * p + 1] == node) {
                int r0 = g_spill[2 * p];
                float n0 = s * g_dis[r0];
                float4 v0 = h4[(size_t)r0 * 32 + lane];
                acc.x += n0 * v0.x; acc.y += n0 * v0.y;
                acc.z += n0 * v0.z; acc.w += n0 * v0.w;
            }
        }
    }

    ((float4*)out)[(size_t)node * 32 + lane] = acc;
}

// ---------------------------------------------------------------------------
extern "C" void kernel_launch(void* const* d_in, const int* in_sizes, int n_in,
                              void* d_out, int out_size) {
    const float* x  = (const float*)d_in[0];
    const void*  ei = d_in[1];
    const float* W  = (const float*)d_in[2];
    const float* b  = (const float*)d_in[3];
    float* out = (float*)d_out;

    const int n  = in_sizes[0] / FDIM;   // 50000
    const int ne = in_sizes[1] / 2;      // 500000

    static cudaStream_t s_side = nullptr;
    static cudaEvent_t  ev_fork = nullptr, ev_join = nullptr;
    if (s_side == nullptr) {
        cudaStreamCreateWithFlags(&s_side, cudaStreamNonBlocking);
        cudaEventCreateWithFlags(&ev_fork, cudaEventDisableTiming);
        cudaEventCreateWithFlags(&ev_join, cudaEventDisableTiming);
    }

    // fork: gemm runs concurrently with the bucket build
    cudaEventRecord(ev_fork, 0);
    cudaStreamWaitEvent(s_side, ev_fork, 0);
    k_gemm<<<(n + ROWS_PB - 1) / ROWS_PB, FDIM, 0, s_side>>>(x, W, n);
    cudaEventRecord(ev_join, s_side);

    // main chain: direct bucket build (no count/scan kernels)
    k_setup <<<(n + 255) / 256, 256>>>((const unsigned long long*)ei, n);
    k_bucket<<<(ne + 256 * EPT - 1) / (256 * EPT), 256>>>(ei, ne);
    k_dis   <<<(n + 255) / 256, 256>>>(n);

    // join, then aggregate (needs both h and the buckets)
    cudaStreamWaitEvent(0, ev_join, 0);
    k_aggregate<<<(n * 32 + 255) / 256, 256>>>(b, out, n);
}